// round 10
// baseline (speedup 1.0000x reference)
#include <cuda_runtime.h>
#include <math.h>

// Problem constants (shapes fixed by setup_inputs)
#define N_   131072
#define D_   64
#define K_   2048
#define RPB  128              // rows per block
#define CPC  256              // codes per smem chunk
#define NCH  (K_ / CPC)       // 8 chunks
#define XDS  136              // xs_dup stride in u64 (128 rows + pad)
#define TPB  256
#define GRID (N_ / RPB)       // 1024 blocks

typedef unsigned int u32;
typedef unsigned long long u64;

// Device scratch (no allocations allowed)
__device__ __align__(16) float g_en  [K_ * D_];   // normalized codebook [k][d]
__device__ __align__(16) float g_ent [K_ * D_];   // chunk-transposed: [chunk][d][c]
__device__ __align__(16) float g_see [K_];        // sum(en^2) per code
__device__ float g_part[GRID];                    // per-block loss partials

// ---- smem byte offsets ----
#define OFF_XS    0           // 69632   xs_dup u64[64][136]  ({v,v} pairs)
#define OFF_B0    69632       // 65536   B buf0 f32 [64][256]
#define OFF_B1    135168      // 65536   B buf1
#define OFF_SEES  200704      // 8192    see[2048]
#define DYNSMEM   208896

// ---------------- helpers ----------------
__device__ __forceinline__ u32 smem_u32(const void* p) {
    u32 a; asm("{ .reg .u64 t; cvta.to.shared.u64 t, %1; cvt.u32.u64 %0, t; }" : "=r"(a) : "l"(p));
    return a;
}
__device__ __forceinline__ void cp16(u32 dst, const void* src) {
    asm volatile("cp.async.cg.shared.global [%0], [%1], 16;" :: "r"(dst), "l"(src) : "memory");
}
__device__ __forceinline__ void cp_commit() { asm volatile("cp.async.commit_group;" ::: "memory"); }
template<int W> __device__ __forceinline__ void cp_wait() {
    asm volatile("cp.async.wait_group %0;" :: "n"(W) : "memory");
}
__device__ __forceinline__ u64 dup2(float v) {
    u64 r; asm("mov.b64 %0, {%1, %1};" : "=l"(r) : "r"(__float_as_uint(v))); return r;
}
__device__ __forceinline__ u64 fma2(u64 a, u64 b, u64 c) {
    u64 d; asm("fma.rn.f32x2 %0, %1, %2, %3;" : "=l"(d) : "l"(a), "l"(b), "l"(c)); return d;
}
__device__ __forceinline__ void unpack2(u64 v, float& lo, float& hi) {
    asm("mov.b64 {%0, %1}, %2;" : "=f"(lo), "=f"(hi) : "l"(v));
}

// ---------------------------------------------------------------------------
// Kernel 1: normalize embeddings -> row-major + chunk-transposed + see[k].
// One warp per code row (D=64 -> 2 elems/lane).   (identical to R2)
// ---------------------------------------------------------------------------
__global__ void vq_norm_emb(const float* __restrict__ emb) {
    int w    = (blockIdx.x * blockDim.x + threadIdx.x) >> 5;   // code index
    int lane = threadIdx.x & 31;
    if (w >= K_) return;
    float v0 = emb[w * 64 + lane];
    float v1 = emb[w * 64 + lane + 32];
    float s  = v0 * v0 + v1 * v1;
    #pragma unroll
    for (int o = 16; o > 0; o >>= 1) s += __shfl_xor_sync(0xffffffffu, s, o);
    float inv = 1.0f / fmaxf(sqrtf(s), 1e-12f);
    float e0 = v0 * inv, e1 = v1 * inv;
    g_en[w * 64 + lane]      = e0;
    g_en[w * 64 + lane + 32] = e1;
    float t = e0 * e0 + e1 * e1;   // see from ROUNDED values (matches reference)
    #pragma unroll
    for (int o = 16; o > 0; o >>= 1) t += __shfl_xor_sync(0xffffffffu, t, o);
    if (lane == 0) g_see[w] = t;
    int ch = w >> 8, c = w & (CPC - 1);
    g_ent[(ch * 64 + lane)      * CPC + c] = e0;
    g_ent[(ch * 64 + lane + 32) * CPC + c] = e1;
}

// ---------------------------------------------------------------------------
// Kernel 2: exact FFMA2 argmin (R2 structure) with pre-duplicated A operands.
// Thread tile 8 rows (ty) x 16 codes (tx: 8 f32x2 pairs); 8 chunks of 256.
// ---------------------------------------------------------------------------
extern __shared__ char smem_[];

__global__ void __launch_bounds__(TPB, 1)
vq_main(const float* __restrict__ x, float* __restrict__ out, int out_size) {
    char* base = smem_;
    u64*   xsd  = (u64*)  (base + OFF_XS);    // [64][XDS] {v,v} pairs
    float* sees = (float*)(base + OFF_SEES);

    int tid  = threadIdx.x;
    int tx   = tid & 15;           // code-pair group
    int ty   = tid >> 4;           // row group (8 rows)
    int rowbase = blockIdx.x * RPB;

    // ---- prefetch B chunk 0 (64KB) via cp.async ----
    {
        u32 dst = smem_u32(base + OFF_B0) + (u32)tid * 16u;
        const char* src = (const char*)g_ent;
        #pragma unroll
        for (int i = 0; i < 16; i++)
            cp16(dst + (u32)i * (TPB * 16u), src + (size_t)(i * TPB + tid) * 16);
        cp_commit();
    }

    // ---- load all see's into smem (8KB) ----
    #pragma unroll
    for (int i = 0; i < 8; i++) sees[i * TPB + tid] = g_see[i * TPB + tid];

    // ---- load x tile, transposed, duplicated {v,v} ----
    #pragma unroll
    for (int i = 0; i < 32; i++) {
        int e = i * TPB + tid;
        int r = e >> 6, d = e & 63;
        xsd[d * XDS + r] = dup2(x[(rowbase + r) * 64 + d]);
    }
    __syncthreads();

    // ---- normalize rows (one thread per row), rewrite duplicated ----
    if (tid < RPB) {
        float s = 0.f;
        #pragma unroll
        for (int d = 0; d < 64; d++) {
            float v = *(const float*)(xsd + d * XDS + tid);
            s += v * v;
        }
        float inv = 1.0f / fmaxf(sqrtf(s), 1e-12f);
        #pragma unroll
        for (int d = 0; d < 64; d++) {
            float v = *(const float*)(xsd + d * XDS + tid) * inv;
            xsd[d * XDS + tid] = dup2(v);
        }
    }
    // (sync before first compute happens inside the chunk loop)

    float minv[8], minkf[8], kf0[8];
    #pragma unroll
    for (int j = 0; j < 8; j++) { minv[j] = 3.4e38f; minkf[j] = 0.f; }
    #pragma unroll
    for (int p = 0; p < 8; p++) kf0[p] = (float)(2 * (tx + 16 * p));
    const u64 M2 = dup2(-2.0f);
    float chbase = 0.f;

    for (int ch = 0; ch < NCH; ch++) {
        if (ch + 1 < NCH) {
            u32 dst = smem_u32(base + (((ch + 1) & 1) ? OFF_B1 : OFF_B0))
                      + (u32)tid * 16u;
            const char* src = (const char*)g_ent + (size_t)(ch + 1) * 65536;
            #pragma unroll
            for (int i = 0; i < 16; i++)
                cp16(dst + (u32)i * (TPB * 16u), src + (size_t)(i * TPB + tid) * 16);
            cp_commit();
            cp_wait<1>();     // chunk ch has landed
        } else {
            cp_wait<0>();
        }
        __syncthreads();

        const u64* eb = (const u64*)(base + ((ch & 1) ? OFF_B1 : OFF_B0));

        u64 acc[8][8];
        #pragma unroll
        for (int j = 0; j < 8; j++)
            #pragma unroll
            for (int p = 0; p < 8; p++) acc[j][p] = 0ull;

        #pragma unroll 4
        for (int d = 0; d < 64; d++) {
            u64 A[8];
            #pragma unroll
            for (int j = 0; j < 8; j++) A[j] = xsd[d * XDS + ty * 8 + j];  // LDS.64 broadcast
            u64 B[8];
            #pragma unroll
            for (int p = 0; p < 8; p++) B[p] = eb[d * (CPC / 2) + tx + 16 * p];
            #pragma unroll
            for (int j = 0; j < 8; j++)
                #pragma unroll
                for (int p = 0; p < 8; p++)
                    acc[j][p] = fma2(A[j], B[p], acc[j][p]);
        }

        // argmin epilogue: compare v = see - 2*dot (sxx is row-constant)
        const u64* seeb = (const u64*)(sees + ch * CPC);
        #pragma unroll
        for (int p = 0; p < 8; p++) {
            u64 S = seeb[tx + 16 * p];
            float klo = kf0[p] + chbase;
            #pragma unroll
            for (int j = 0; j < 8; j++) {
                u64 v2 = fma2(M2, acc[j][p], S);
                float lo, hi; unpack2(v2, lo, hi);
                bool c1 = lo < minv[j];
                minv[j]  = c1 ? lo  : minv[j];
                minkf[j] = c1 ? klo : minkf[j];
                bool c2 = hi < minv[j];
                minv[j]  = c2 ? hi           : minv[j];
                minkf[j] = c2 ? (klo + 1.0f) : minkf[j];
            }
        }
        chbase += (float)CPC;
        __syncthreads();     // everyone done reading this buffer
    }

    // ---- reduce argmin across the 16 code-group threads per row ----
    float2* red = (float2*)(base + OFF_B0);   // [RPB][16] (val, idx)
    #pragma unroll
    for (int j = 0; j < 8; j++)
        red[(ty * 8 + j) * 16 + tx] = make_float2(minv[j], minkf[j]);
    __syncthreads();

    float lsum = 0.f;
    if (tid < RPB) {
        float bv = 3.5e38f, bkf = 0.f;
        #pragma unroll
        for (int t = 0; t < 16; t++) {
            float2 e2 = red[tid * 16 + t];
            if (e2.x < bv || (e2.x == bv && e2.y < bkf)) { bv = e2.x; bkf = e2.y; }
        }
        int bk = (int)bkf;
        // reference re-normalizes the gathered code (idempotent, replicated)
        float inv2 = 1.0f / fmaxf(sqrtf(g_see[bk]), 1e-12f);
        const float* erow = g_en + bk * 64;
        #pragma unroll
        for (int d = 0; d < 64; d++) {
            float xnv  = *(const float*)(xsd + d * XDS + tid);
            float qd   = erow[d] * inv2;
            float diff = qd - xnv;
            lsum += diff * diff;
            *(float*)(xsd + d * XDS + tid) = xnv + diff;      // quantized_st (lo half)
        }
        if (out_size >= N_ * D_ + 1 + N_)
            out[N_ * D_ + 1 + rowbase + tid] = bkf;
    }
    __syncthreads();

    // ---- coalesced store of quantized_st (read lo halves) ----
    #pragma unroll
    for (int i = 0; i < 32; i++) {
        int e = i * TPB + tid;
        out[rowbase * 64 + e] = *(const float*)(xsd + (e & 63) * XDS + (e >> 6));
    }

    // ---- deterministic block loss reduction (reuse sees region) ----
    float* redl = (float*)(base + OFF_SEES);
    if (tid < RPB) redl[tid] = lsum;
    __syncthreads();
    for (int s = 64; s > 0; s >>= 1) {
        if (tid < s) redl[tid] += redl[tid + s];
        __syncthreads();
    }
    if (tid == 0) g_part[blockIdx.x] = redl[0];
}

// ---------------------------------------------------------------------------
// Kernel 3: deterministic final loss reduction.
// loss = q_latent + 0.25*e_latent = 1.25 * mean((q - xn)^2)
// ---------------------------------------------------------------------------
__global__ void vq_final(float* __restrict__ out, int out_size) {
    __shared__ float sm[256];
    int tid = threadIdx.x;
    float s = g_part[tid] + g_part[tid + 256] + g_part[tid + 512] + g_part[tid + 768];
    sm[tid] = s;
    __syncthreads();
    for (int st = 128; st > 0; st >>= 1) {
        if (tid < st) sm[tid] += sm[tid + st];
        __syncthreads();
    }
    if (tid == 0 && out_size > N_ * D_)
        out[N_ * D_] = 1.25f * (sm[0] / (float)(N_ * D_));
}

// ---------------------------------------------------------------------------
extern "C" void kernel_launch(void* const* d_in, const int* in_sizes, int n_in,
                              void* d_out, int out_size) {
    const float* x;
    const float* emb;
    if (n_in >= 2 && in_sizes[0] >= in_sizes[1]) {
        x = (const float*)d_in[0]; emb = (const float*)d_in[1];
    } else {
        x = (const float*)d_in[1]; emb = (const float*)d_in[0];
    }

    cudaFuncSetAttribute(vq_main, cudaFuncAttributeMaxDynamicSharedMemorySize, DYNSMEM);

    vq_norm_emb<<<K_ / 8, 256>>>(emb);
    vq_main<<<GRID, TPB, DYNSMEM>>>(x, (float*)d_out, out_size);
    vq_final<<<1, 256>>>((float*)d_out, out_size);
}

// round 11
// speedup vs baseline: 1.1327x; 1.1327x over previous
#include <cuda_runtime.h>
#include <cuda_bf16.h>
#include <math.h>

#define N_   131072
#define D_   64
#define K_   2048
#define RPB  128              // rows per block
#define CPC  256              // codes per chunk
#define NCH  (K_ / CPC)       // 8 chunks
#define XSS  132              // padded xs stride (floats)
#define TPB  1024
#define GRID (N_ / RPB)       // 1024 blocks
#define MARG    0.009f        // bf16 screening margin (validated R4/R5)
#define MARG_FX 299
#define QTH  16               // per-thread queue capacity
#define BPAD 72               // bf16 row pad: 144B rows, conflict-free LDS

typedef unsigned int u32;
typedef unsigned long long u64;

// Device scratch (no allocations allowed)
__device__ __align__(16) float         g_en  [K_ * D_];
__device__ __align__(16) float         g_see [K_];
__device__ __align__(16) __nv_bfloat16 g_enbp[K_ * BPAD];
__device__ float g_part[GRID];

// ---- smem byte offsets ----
#define OFF_XS   0            // 33792   xs fp32 [64][132]
#define OFF_MA   33792        // 18432   A bf16 [128][72h]
#define OFF_MB0  52224        // 36864   B buf0 [256][72h]
#define OFF_MB1  89088        // 36864   B buf1
#define OFF_SXX  125952       // 512
#define OFF_RB   126464       // 1024    u64[128] packed (valbits, code)
#define OFF_Q    127488       // 65536   queues, interleaved [i][tid]
#define DYNSMEM  193024

// ---------------- helpers ----------------
__device__ __forceinline__ u32 smem_u32(const void* p) {
    u32 a; asm("{ .reg .u64 t; cvta.to.shared.u64 t, %1; cvt.u32.u64 %0, t; }" : "=r"(a) : "l"(p));
    return a;
}
__device__ __forceinline__ void cp16(u32 dst, const void* src) {
    asm volatile("cp.async.cg.shared.global [%0], [%1], 16;" :: "r"(dst), "l"(src) : "memory");
}
__device__ __forceinline__ void cp_commit() { asm volatile("cp.async.commit_group;" ::: "memory"); }
template<int W> __device__ __forceinline__ void cp_wait() {
    asm volatile("cp.async.wait_group %0;" :: "n"(W) : "memory");
}
__device__ __forceinline__ void mma16816(float* c, const u32* a, u32 b0, u32 b1) {
    asm volatile("mma.sync.aligned.m16n8k16.row.col.f32.bf16.bf16.f32 "
        "{%0,%1,%2,%3}, {%4,%5,%6,%7}, {%8,%9}, {%0,%1,%2,%3};"
        : "+f"(c[0]), "+f"(c[1]), "+f"(c[2]), "+f"(c[3])
        : "r"(a[0]), "r"(a[1]), "r"(a[2]), "r"(a[3]), "r"(b0), "r"(b1));
}
__device__ __forceinline__ u32 fix16(float v) {
    float c = fminf(fmaxf(fmaf(v, 32767.f, 32768.f), 0.f), 65535.f);
    return (u32)c;
}
// exact fp32 rescore (identical formula/order to passing kernels) + atomicMin key
__device__ __noinline__ void exact_rescore(const float* xs, const float* sxx,
                                           u64* rbest, int row, int code) {
    float dot = 0.f;
    const float* er = g_en + code * 64;
    #pragma unroll
    for (int d = 0; d < 64; d++) dot = fmaf(xs[d * XSS + row], er[d], dot);
    float val = fmaf(-2.0f, dot, sxx[row] + g_see[code]);
    u32 vb = __float_as_uint(val);
    vb = (vb & 0x80000000u) ? ~vb : (vb | 0x80000000u);     // order-preserving
    u64 key = ((u64)vb << 32) | (u32)code;
    atomicMin(rbest + row, key);                            // min val, tie -> min idx
}

// ---------------------------------------------------------------------------
// Kernel 1: normalize embeddings -> g_en (fp32), g_see, g_enbp (bf16 padded).
// ---------------------------------------------------------------------------
__global__ void vq_norm_emb(const float* __restrict__ emb) {
    int w    = (blockIdx.x * blockDim.x + threadIdx.x) >> 5;
    int lane = threadIdx.x & 31;
    if (w >= K_) return;
    float v0 = emb[w * 64 + lane];
    float v1 = emb[w * 64 + lane + 32];
    float s  = v0 * v0 + v1 * v1;
    #pragma unroll
    for (int o = 16; o > 0; o >>= 1) s += __shfl_xor_sync(0xffffffffu, s, o);
    float inv = 1.0f / fmaxf(sqrtf(s), 1e-12f);
    float e0 = v0 * inv, e1 = v1 * inv;
    g_en[w * 64 + lane]      = e0;
    g_en[w * 64 + lane + 32] = e1;
    float t = e0 * e0 + e1 * e1;   // see from ROUNDED values (matches reference)
    #pragma unroll
    for (int o = 16; o > 0; o >>= 1) t += __shfl_xor_sync(0xffffffffu, t, o);
    if (lane == 0) g_see[w] = t;
    g_enbp[w * BPAD + lane]      = __float2bfloat16(e0);
    g_enbp[w * BPAD + lane + 32] = __float2bfloat16(e1);
}

// ---------------------------------------------------------------------------
// Kernel 2: HMMA bf16 screening at 32 warps (8/SMSP) + exact fp32 rescore.
// Warp tile: 16 rows x 64 codes per 256-chunk; 8(wy) x 4(wx) warps.
// ---------------------------------------------------------------------------
extern __shared__ char smem_[];

__global__ void __launch_bounds__(TPB, 1)
vq_main(const float* __restrict__ x, float* __restrict__ out, int out_size) {
    char* base = smem_;
    float* xs    = (float*)(base + OFF_XS);
    float* sxx   = (float*)(base + OFF_SXX);
    u64*   rbest = (u64*)  (base + OFF_RB);
    u32*   qbuf  = (u32*)  (base + OFF_Q);    // entry i of thread t at [i*TPB + t]

    int tid  = threadIdx.x;
    int warp = tid >> 5, lane = tid & 31;
    int g  = lane >> 2;            // groupID (0..7)
    int tq = lane & 3;             // thread-in-group
    int wy = warp & 7;             // 16-row block
    int wx = warp >> 3;            // 64-code quarter of each 256-chunk
    int rowbase = blockIdx.x * RPB;

    if (tid < RPB) rbest[tid] = 0xFFFFFFFFFFFFFFFFull;

    // prefetch B chunk 0: 36864 B contiguous (g_enbp rows are 144B packed)
    {
        u32 dst = smem_u32(base + OFF_MB0);
        const char* src = (const char*)g_enbp;
        #pragma unroll
        for (int i = 0; i < 3; i++) {
            int idx = i * TPB + tid;
            if (idx < 2304) cp16(dst + (u32)idx * 16u, src + (size_t)idx * 16);
        }
        cp_commit();
    }

    // load x tile, transposed
    #pragma unroll
    for (int i = 0; i < 8; i++) {
        int e = i * TPB + tid;
        int r = e >> 6, d = e & 63;
        xs[d * XSS + r] = x[(rowbase + r) * 64 + d];
    }
    __syncthreads();

    // normalize rows; sxx
    if (tid < RPB) {
        float s = 0.f;
        #pragma unroll
        for (int d = 0; d < 64; d++) { float v = xs[d * XSS + tid]; s += v * v; }
        float inv = 1.0f / fmaxf(sqrtf(s), 1e-12f);
        float s2 = 0.f;
        #pragma unroll
        for (int d = 0; d < 64; d++) {
            float v = xs[d * XSS + tid] * inv;
            xs[d * XSS + tid] = v;
            s2 += v * v;
        }
        sxx[tid] = s2;
    }
    __syncthreads();

    // A tile bf16 [row][72 halves]
    #pragma unroll
    for (int i = 0; i < 8; i++) {
        int e = i * TPB + tid;
        int r = e >> 6, d = e & 63;
        *(__nv_bfloat16*)(base + OFF_MA + r * 144 + d * 2) =
            __float2bfloat16(xs[d * XSS + r]);
    }
    __syncthreads();

    // A fragments (persist across all chunks): mapping validated R4/R5
    u32 af[4][4];
    {
        int r0 = wy * 16 + g;
        #pragma unroll
        for (int k = 0; k < 4; k++) {
            int c0 = (k * 16 + tq * 2) * 2;
            af[k][0] = *(const u32*)(base + OFF_MA + r0 * 144 + c0);
            af[k][1] = *(const u32*)(base + OFF_MA + (r0 + 8) * 144 + c0);
            af[k][2] = *(const u32*)(base + OFF_MA + r0 * 144 + c0 + 16);
            af[k][3] = *(const u32*)(base + OFF_MA + (r0 + 8) * 144 + c0 + 16);
        }
    }

    float rm[2] = { -1e30f, -1e30f };
    int qn = 0;

    for (int ch = 0; ch < NCH; ch++) {
        if (ch + 1 < NCH) {
            u32 dst = smem_u32(base + (((ch + 1) & 1) ? OFF_MB1 : OFF_MB0));
            const char* src = (const char*)g_enbp + (size_t)(ch + 1) * 36864;
            #pragma unroll
            for (int i = 0; i < 3; i++) {
                int idx = i * TPB + tid;
                if (idx < 2304) cp16(dst + (u32)idx * 16u, src + (size_t)idx * 16);
            }
            cp_commit();
            cp_wait<1>();     // chunk ch landed
        } else {
            cp_wait<0>();
        }
        __syncthreads();

        const char* Bs = base + ((ch & 1) ? OFF_MB1 : OFF_MB0);

        #pragma unroll
        for (int ng = 0; ng < 2; ng++) {
            float acc[4][4];
            #pragma unroll
            for (int nt = 0; nt < 4; nt++)
                #pragma unroll
                for (int q = 0; q < 4; q++) acc[nt][q] = 0.f;

            #pragma unroll
            for (int k = 0; k < 4; k++) {
                #pragma unroll
                for (int nt = 0; nt < 4; nt++) {
                    int cr = wx * 64 + ng * 32 + nt * 8 + g;
                    int co = k * 32 + tq * 4;
                    u32 b0 = *(const u32*)(Bs + cr * 144 + co);
                    u32 b1 = *(const u32*)(Bs + cr * 144 + co + 16);
                    mma16816(acc[nt], af[k], b0, b1);
                }
            }

            int cbase = ch * CPC + wx * 64 + ng * 32 + tq * 2;

            // group-max fast path per row stream (sid 0: row g, sid 1: row g+8)
            #pragma unroll
            for (int sid = 0; sid < 2; sid++) {
                int qh = sid * 2;
                float gm = fmaxf(fmaxf(acc[0][qh], acc[0][qh + 1]),
                                 fmaxf(acc[1][qh], acc[1][qh + 1]));
                gm = fmaxf(gm, fmaxf(fmaxf(acc[2][qh], acc[2][qh + 1]),
                                     fmaxf(acc[3][qh], acc[3][qh + 1])));
                if (gm > rm[sid] - MARG) {                // rare slow path
                    float th = fmaxf(rm[sid], gm) - MARG;
                    #pragma unroll
                    for (int nt = 0; nt < 4; nt++) {
                        #pragma unroll
                        for (int qq = 0; qq < 2; qq++) {
                            float v = acc[nt][qh + qq];
                            if (v > th) {
                                int code = cbase + nt * 8 + qq;
                                if (qn >= QTH) {           // purge stale entries
                                    int w2 = 0;
                                    for (int i = 0; i < qn; i++) {
                                        u32 e = qbuf[i * TPB + tid];
                                        int ss = (e >> 11) & 1;
                                        if ((e >> 16) + 4 >= fix16(rm[ss] - MARG))
                                            qbuf[w2++ * TPB + tid] = e;
                                    }
                                    qn = w2;
                                }
                                if (qn < QTH) {
                                    qbuf[qn * TPB + tid] =
                                        (fix16(v) << 16) | ((u32)sid << 11) | (u32)code;
                                    qn++;
                                } else {                   // guaranteed-correct fallback
                                    exact_rescore(xs, sxx, rbest,
                                        wy * 16 + sid * 8 + g, code);
                                }
                            }
                        }
                    }
                }
                rm[sid] = fmaxf(rm[sid], gm);
            }
        }
        __syncthreads();
    }

    // refilter queue vs final per-thread stream max; exact-rescore survivors
    for (int i = 0; i < qn; i++) {
        u32 e = qbuf[i * TPB + tid];
        int code = e & 2047;
        int sid  = (e >> 11) & 1;
        if ((e >> 16) + MARG_FX >= fix16(rm[sid]))
            exact_rescore(xs, sxx, rbest, wy * 16 + sid * 8 + g, code);
    }
    __syncthreads();

    // ---- per-row final: quantized_st, idx, loss ----
    float lsum = 0.f;
    if (tid < RPB) {
        int bk = (int)(rbest[tid] & 2047u);
        float inv2 = 1.0f / fmaxf(sqrtf(g_see[bk]), 1e-12f);
        const float* erow = g_en + bk * 64;
        #pragma unroll
        for (int d = 0; d < 64; d++) {
            float xnv  = xs[d * XSS + tid];
            float qd   = erow[d] * inv2;
            float diff = qd - xnv;
            lsum += diff * diff;
            xs[d * XSS + tid] = xnv + diff;
        }
        if (out_size >= N_ * D_ + 1 + N_)
            out[N_ * D_ + 1 + rowbase + tid] = (float)bk;
    }
    __syncthreads();

    // coalesced store of quantized_st
    #pragma unroll
    for (int i = 0; i < 8; i++) {
        int e = i * TPB + tid;
        out[rowbase * 64 + e] = xs[(e & 63) * XSS + (e >> 6)];
    }

    // deterministic block loss reduction (reuse sxx-adjacent region is unsafe;
    // use qbuf space which is dead now)
    float* red = (float*)(base + OFF_Q);
    if (tid < RPB) red[tid] = lsum;
    __syncthreads();
    for (int s = 64; s > 0; s >>= 1) {
        if (tid < s) red[tid] += red[tid + s];
        __syncthreads();
    }
    if (tid == 0) g_part[blockIdx.x] = red[0];
}

// ---------------------------------------------------------------------------
// Kernel 3: deterministic final loss reduction.
// loss = q_latent + 0.25*e_latent = 1.25 * mean((q - xn)^2)
// ---------------------------------------------------------------------------
__global__ void vq_final(float* __restrict__ out, int out_size) {
    __shared__ float sm[256];
    int tid = threadIdx.x;
    float s = g_part[tid] + g_part[tid + 256] + g_part[tid + 512] + g_part[tid + 768];
    sm[tid] = s;
    __syncthreads();
    for (int st = 128; st > 0; st >>= 1) {
        if (tid < st) sm[tid] += sm[tid + st];
        __syncthreads();
    }
    if (tid == 0 && out_size > N_ * D_)
        out[N_ * D_] = 1.25f * (sm[0] / (float)(N_ * D_));
}

// ---------------------------------------------------------------------------
extern "C" void kernel_launch(void* const* d_in, const int* in_sizes, int n_in,
                              void* d_out, int out_size) {
    const float* x;
    const float* emb;
    if (n_in >= 2 && in_sizes[0] >= in_sizes[1]) {
        x = (const float*)d_in[0]; emb = (const float*)d_in[1];
    } else {
        x = (const float*)d_in[1]; emb = (const float*)d_in[0];
    }

    cudaFuncSetAttribute(vq_main, cudaFuncAttributeMaxDynamicSharedMemorySize, DYNSMEM);

    vq_norm_emb<<<K_ / 8, 256>>>(emb);
    vq_main<<<GRID, TPB, DYNSMEM>>>(x, (float*)d_out, out_size);
    vq_final<<<1, 256>>>((float*)d_out, out_size);
}